// round 13
// baseline (speedup 1.0000x reference)
#include <cuda_runtime.h>
#include <cstdint>

// ---------------------------------------------------------------------------
// AttentionMapLayer (fused, single kernel):
//   out[b,h,w,c] = (t_hat[b,h]*s_hat[b,w] + roi[w]) * ipt[b,h,w,c]
//   s_hat = l2_normalize(s_o, axis=1)  (B,25)
//   t_hat = l2_normalize(t_o, axis=1)  (B,300)
//   roi[w] = 1 for w in {3,8,12,14,17,19}
// B=1024, H=300, W=25, C=16 -> 983 MB HBM traffic.
//
// R13: fuse normalization into the stream kernel. Each block's 256 (b,h,w)
// triples span <=2 batches; the block redundantly computes both batches'
// inverse norms from L2-resident t_o/s_o, hidden behind the 4 outstanding
// ipt DRAM loads issued first. Eliminates the separate normalize kernel
// (+launch/graph node), ~10us of non-stream time.
// ---------------------------------------------------------------------------

#define HEIGHT 300
#define WIDTH  25
#define HW     (HEIGHT * WIDTH)     // 7500 triples per batch

// roi bitmask over w in [0,25)
#define ROI_MASK ((1u<<3)|(1u<<8)|(1u<<12)|(1u<<14)|(1u<<17)|(1u<<19))

#define ITEMS 4
#define BLKTHREADS 256
#define TILE4 (BLKTHREADS * ITEMS)   // 1024 float4 per block = 256 triples

__global__ __launch_bounds__(BLKTHREADS)
void fused_attn_kernel(const float*  __restrict__ s_o,
                       const float*  __restrict__ t_o,
                       const float4* __restrict__ ipt,
                       float4*       __restrict__ out,
                       int total4, int B)
{
    const int tid  = threadIdx.x;
    const int base = blockIdx.x * TILE4 + tid;

    // ---- Phase 1: issue all 4 main stream loads (independent, front-batched)
    int    idx[ITEMS];
    bool   ok[ITEMS];
    float4 v[ITEMS];
    #pragma unroll
    for (int j = 0; j < ITEMS; ++j) {
        idx[j] = base + j * BLKTHREADS;
        ok[j]  = idx[j] < total4;
        if (ok[j]) v[j] = ipt[idx[j]];
    }

    // ---- Phase 2: block-cooperative inverse norms for the (<=2) batches this
    // block touches. t_o/s_o are tiny (1.3 MB) and L2-resident; this latency
    // hides under the outstanding Phase-1 DRAM loads.
    const int p0 = blockIdx.x * (TILE4 / 4);   // first (b,h,w) triple
    const int b0 = p0 / HW;
    const int b1 = min(b0 + 1, B - 1);

    float a0 = 0.0f, a1 = 0.0f;                // sum t^2 for b0, b1
    #pragma unroll
    for (int i = tid; i < HEIGHT; i += BLKTHREADS) {
        float x0 = t_o[b0 * HEIGHT + i]; a0 += x0 * x0;
        float x1 = t_o[b1 * HEIGHT + i]; a1 += x1 * x1;
    }
    float c0 = 0.0f, c1 = 0.0f;                // sum s^2 for b0, b1
    if (tid < WIDTH) {
        float y0 = s_o[b0 * WIDTH + tid]; c0 = y0 * y0;
        float y1 = s_o[b1 * WIDTH + tid]; c1 = y1 * y1;
    }

    // warp-level reduce of all 4 accumulators
    #pragma unroll
    for (int off = 16; off > 0; off >>= 1) {
        a0 += __shfl_down_sync(0xffffffffu, a0, off);
        a1 += __shfl_down_sync(0xffffffffu, a1, off);
        c0 += __shfl_down_sync(0xffffffffu, c0, off);
        c1 += __shfl_down_sync(0xffffffffu, c1, off);
    }

    __shared__ float red[8][4];   // 8 warps x {a0,a1,c0,c1}
    __shared__ float inv[4];      // {inv_t0, inv_t1, inv_s0, inv_s1}
    const int warp = tid >> 5;
    const int lane = tid & 31;
    if (lane == 0) {
        red[warp][0] = a0; red[warp][1] = a1;
        red[warp][2] = c0; red[warp][3] = c1;
    }
    __syncthreads();
    if (tid < 4) {
        float s = 0.0f;
        #pragma unroll
        for (int wq = 0; wq < 8; ++wq) s += red[wq][tid];
        inv[tid] = rsqrtf(fmaxf(s, 1e-12f));
    }
    __syncthreads();
    const float it0 = inv[0], it1 = inv[1], is0 = inv[2], is1 = inv[3];

    // ---- Phase 3: compute scale, apply, store
    #pragma unroll
    for (int j = 0; j < ITEMS; ++j) {
        if (ok[j]) {
            const int p  = idx[j] >> 2;       // linear (b,h,w)
            const int w  = p % WIDTH;
            const int bh = p / WIDTH;         // b*HEIGHT + h
            const int b  = bh / HEIGHT;

            const float it = (b == b0) ? it0 : it1;
            const float is = (b == b0) ? is0 : is1;
            const float roi = ((ROI_MASK >> w) & 1u) ? 1.0f : 0.0f;

            const float th = __ldg(&t_o[bh]) * it;              // L1/L2 hit
            const float sh = __ldg(&s_o[b * WIDTH + w]) * is;   // L1/L2 hit
            const float sc = fmaf(th, sh, roi);

            float4 r = v[j];
            r.x *= sc; r.y *= sc; r.z *= sc; r.w *= sc;
            out[idx[j]] = r;
        }
    }
}

// ---------------------------------------------------------------------------
// Launch
// ---------------------------------------------------------------------------
extern "C" void kernel_launch(void* const* d_in, const int* in_sizes, int n_in,
                              void* d_out, int out_size)
{
    // Identify inputs by size (robust to metadata ordering):
    //   ipt = B*300*25*16 (largest), t_o = B*300, s_o = B*25
    int ipt_i = 0;
    for (int k = 1; k < n_in; ++k)
        if (in_sizes[k] > in_sizes[ipt_i]) ipt_i = k;
    int a = -1, c = -1;
    for (int k = 0; k < n_in; ++k) {
        if (k == ipt_i) continue;
        if (a < 0) a = k; else c = k;
    }
    int s_i = (in_sizes[a] < in_sizes[c]) ? a : c;
    int t_i = (s_i == a) ? c : a;

    const float* s_o = (const float*)d_in[s_i];
    const float* t_o = (const float*)d_in[t_i];
    const float* ipt = (const float*)d_in[ipt_i];
    float* out = (float*)d_out;

    const int B = in_sizes[t_i] / HEIGHT;   // 1024

    const int total4 = out_size / 4;                    // 30,720,000
    const int blocks = (total4 + TILE4 - 1) / TILE4;    // 30,000
    fused_attn_kernel<<<blocks, BLKTHREADS>>>(
        s_o, t_o, (const float4*)ipt, (float4*)out, total4, B);
}

// round 14
// speedup vs baseline: 1.0792x; 1.0792x over previous
#include <cuda_runtime.h>
#include <cstdint>

// ---------------------------------------------------------------------------
// AttentionMapLayer: out[b,h,w,c] = (t_hat[b,h]*s_hat[b,w] + roi[w]) * ipt[b,h,w,c]
//   s_hat = l2_normalize(s_o, axis=1)  (B,25)
//   t_hat = l2_normalize(t_o, axis=1)  (B,300)
//   roi[w] = 1 for w in {3,8,12,14,17,19}
// B=1024, H=300, W=25, C=16 -> 983 MB HBM traffic, HBM-bound.
//
// R14: revert to R12 two-kernel design (fusion regressed: barriers throttle
// the LDG stream). Push the streamer: ITEMS=8 (MLP_p1=8, half the blocks),
// __ldcs/__stcs streaming hints on the zero-reuse 983 MB stream.
// ---------------------------------------------------------------------------

#define HEIGHT 300
#define WIDTH  25
#define MAX_B  4096

// roi bitmask over w in [0,25)
#define ROI_MASK ((1u<<3)|(1u<<8)|(1u<<12)|(1u<<14)|(1u<<17)|(1u<<19))

// Scratch for normalized vectors (device globals: allocation-guard safe)
__device__ float g_s_hat[MAX_B * WIDTH];
__device__ float g_t_hat[MAX_B * HEIGHT];

// ---------------------------------------------------------------------------
// Kernel 1: per-batch L2 normalization of s_o (25) and t_o (300).
// One block per batch, 128 threads. One latency-bound wave, ~5us.
// ---------------------------------------------------------------------------
__global__ __launch_bounds__(128)
void normalize_kernel(const float* __restrict__ s_o,
                      const float* __restrict__ t_o)
{
    const int b   = blockIdx.x;
    const int tid = threadIdx.x;

    __shared__ float red[4];  // one slot per warp (128 thr = 4 warps)

    float acc_t = 0.0f;
    for (int i = tid; i < HEIGHT; i += 128) {
        float v = t_o[b * HEIGHT + i];
        acc_t += v * v;
    }
    float acc_s = 0.0f;
    if (tid < WIDTH) {
        float v = s_o[b * WIDTH + tid];
        acc_s = v * v;
    }

    #pragma unroll
    for (int off = 16; off > 0; off >>= 1) {
        acc_t += __shfl_down_sync(0xffffffffu, acc_t, off);
        acc_s += __shfl_down_sync(0xffffffffu, acc_s, off);
    }
    const int warp = tid >> 5;
    const int lane = tid & 31;
    if (lane == 0) red[warp] = acc_t;
    __syncthreads();
    float sum_t = red[0] + red[1] + red[2] + red[3];
    __shared__ float s_sum_sh;
    if (tid == 0) s_sum_sh = acc_s;   // warp0 lane0 holds full s sum (W=25<32)
    __syncthreads();
    float sum_s = s_sum_sh;

    const float inv_t = rsqrtf(fmaxf(sum_t, 1e-12f));
    const float inv_s = rsqrtf(fmaxf(sum_s, 1e-12f));

    for (int i = tid; i < HEIGHT; i += 128)
        g_t_hat[b * HEIGHT + i] = t_o[b * HEIGHT + i] * inv_t;
    if (tid < WIDTH)
        g_s_hat[b * WIDTH + tid] = s_o[b * WIDTH + tid] * inv_s;
}

// ---------------------------------------------------------------------------
// Kernel 2: streaming multiply, 8 float4s per thread, block-strided
// (coalescing preserved: each warp covers 512B contiguous per item).
// Phase 1: all 8 main loads front-batched (MLP_p1=8), evict-first.
// Phase 2: cached scale lookups. Phase 3: FMA + streaming stores.
// ---------------------------------------------------------------------------
#define ITEMS 8
#define BLKTHREADS 256
#define TILE4 (BLKTHREADS * ITEMS)   // 2048 float4 per block

__global__ __launch_bounds__(BLKTHREADS)
void scale_mul_kernel(const float4* __restrict__ ipt,
                      float4* __restrict__ out,
                      int total4)
{
    const int base = blockIdx.x * TILE4 + threadIdx.x;

    int  idx[ITEMS];
    bool ok[ITEMS];
    #pragma unroll
    for (int j = 0; j < ITEMS; ++j) {
        idx[j] = base + j * BLKTHREADS;
        ok[j]  = idx[j] < total4;
    }

    // Phase 1: main stream loads, all independent, evict-first (zero reuse)
    float4 v[ITEMS];
    #pragma unroll
    for (int j = 0; j < ITEMS; ++j)
        if (ok[j]) v[j] = __ldcs(&ipt[idx[j]]);

    // Phase 2: scale operand loads (tiny, cached; t_hat reused 100x, s_hat 4800x)
    float sc[ITEMS];
    #pragma unroll
    for (int j = 0; j < ITEMS; ++j) {
        if (ok[j]) {
            const int p  = idx[j] >> 2;        // linear (b,h,w)
            const int w  = p % WIDTH;
            const int bh = p / WIDTH;          // b*HEIGHT + h
            const int b  = bh / HEIGHT;
            const float roi = ((ROI_MASK >> w) & 1u) ? 1.0f : 0.0f;
            sc[j] = fmaf(__ldg(&g_t_hat[bh]), __ldg(&g_s_hat[b * WIDTH + w]), roi);
        }
    }

    // Phase 3: scale and store (streaming)
    #pragma unroll
    for (int j = 0; j < ITEMS; ++j) {
        if (ok[j]) {
            float4 r = v[j];
            r.x *= sc[j]; r.y *= sc[j]; r.z *= sc[j]; r.w *= sc[j];
            __stcs(&out[idx[j]], r);
        }
    }
}

// ---------------------------------------------------------------------------
// Launch
// ---------------------------------------------------------------------------
extern "C" void kernel_launch(void* const* d_in, const int* in_sizes, int n_in,
                              void* d_out, int out_size)
{
    // Identify inputs by size (robust to metadata ordering):
    //   ipt = B*300*25*16 (largest), t_o = B*300, s_o = B*25
    int ipt_i = 0;
    for (int k = 1; k < n_in; ++k)
        if (in_sizes[k] > in_sizes[ipt_i]) ipt_i = k;
    int a = -1, c = -1;
    for (int k = 0; k < n_in; ++k) {
        if (k == ipt_i) continue;
        if (a < 0) a = k; else c = k;
    }
    int s_i = (in_sizes[a] < in_sizes[c]) ? a : c;
    int t_i = (s_i == a) ? c : a;

    const float* s_o = (const float*)d_in[s_i];
    const float* t_o = (const float*)d_in[t_i];
    const float* ipt = (const float*)d_in[ipt_i];
    float* out = (float*)d_out;

    const int B = in_sizes[t_i] / HEIGHT;   // 1024

    // Kernel 1: normalize (B blocks x 128 threads)
    normalize_kernel<<<B, 128>>>(s_o, t_o);

    // Kernel 2: stream (8 float4 per thread, 2048 float4 per block)
    const int total4 = out_size / 4;                    // 30,720,000
    const int blocks = (total4 + TILE4 - 1) / TILE4;    // 15,000
    scale_mul_kernel<<<blocks, BLKTHREADS>>>((const float4*)ipt, (float4*)out, total4);
}

// round 15
// speedup vs baseline: 1.0893x; 1.0094x over previous
#include <cuda_runtime.h>
#include <cstdint>

// ---------------------------------------------------------------------------
// AttentionMapLayer: out[b,h,w,c] = (t_hat[b,h]*s_hat[b,w] + roi[w]) * ipt[b,h,w,c]
//   s_hat = l2_normalize(s_o, axis=1)  (B,25)
//   t_hat = l2_normalize(t_o, axis=1)  (B,300)
//   roi[w] = 1 for w in {3,8,12,14,17,19}
// B=1024, H=300, W=25, C=16 -> 983 MB HBM stream, HBM-bound (~86% achieved).
//
// R15: streamer back to proven ITEMS=4/occ61% config (+ldcs/stcs hints);
// normalize kernel slimmed to inverse-norms-only (2048 floats out, no second
// pass) -- streamer folds the normalization multiply into its cached scale
// computation (2 extra L1-hit loads + 1 FMUL per item, issue has slack).
// ---------------------------------------------------------------------------

#define HEIGHT 300
#define WIDTH  25
#define MAX_B  4096

// roi bitmask over w in [0,25)
#define ROI_MASK ((1u<<3)|(1u<<8)|(1u<<12)|(1u<<14)|(1u<<17)|(1u<<19))

// Scratch: per-batch inverse L2 norms (device globals: allocation-guard safe)
__device__ float g_inv_t[MAX_B];
__device__ float g_inv_s[MAX_B];

// ---------------------------------------------------------------------------
// Kernel 1: per-batch inverse L2 norms of s_o (25) and t_o (300).
// One block per batch, 128 threads. Pure reduction, 2 floats out per batch.
// ---------------------------------------------------------------------------
__global__ __launch_bounds__(128)
void inv_norm_kernel(const float* __restrict__ s_o,
                     const float* __restrict__ t_o)
{
    const int b   = blockIdx.x;
    const int tid = threadIdx.x;

    __shared__ float red[4];  // one slot per warp

    float acc_t = 0.0f;
    for (int i = tid; i < HEIGHT; i += 128) {
        float v = t_o[b * HEIGHT + i];
        acc_t += v * v;
    }
    float acc_s = 0.0f;
    if (tid < WIDTH) {
        float v = s_o[b * WIDTH + tid];
        acc_s = v * v;
    }

    #pragma unroll
    for (int off = 16; off > 0; off >>= 1) {
        acc_t += __shfl_down_sync(0xffffffffu, acc_t, off);
        acc_s += __shfl_down_sync(0xffffffffu, acc_s, off);
    }
    const int warp = tid >> 5;
    const int lane = tid & 31;
    if (lane == 0) red[warp] = acc_t;
    __syncthreads();
    if (tid == 0) {
        const float sum_t = red[0] + red[1] + red[2] + red[3];
        g_inv_t[b] = rsqrtf(fmaxf(sum_t, 1e-12f));
        g_inv_s[b] = rsqrtf(fmaxf(acc_s, 1e-12f));  // lane0 of warp0 holds full s sum
    }
}

// ---------------------------------------------------------------------------
// Kernel 2: streaming multiply, 4 float4s per thread, block-strided (warp
// covers 512B contiguous per item). Phase 1: 4 front-batched evict-first
// loads (MLP_p1=4). Phase 2: cached scale computation (t_o, s_o, inv norms
// all L1/L2-resident, massive reuse). Phase 3: FMA + streaming stores.
// ---------------------------------------------------------------------------
#define ITEMS 4
#define BLKTHREADS 256
#define TILE4 (BLKTHREADS * ITEMS)   // 1024 float4 per block

__global__ __launch_bounds__(BLKTHREADS)
void scale_mul_kernel(const float*  __restrict__ s_o,
                      const float*  __restrict__ t_o,
                      const float4* __restrict__ ipt,
                      float4*       __restrict__ out,
                      int total4)
{
    const int base = blockIdx.x * TILE4 + threadIdx.x;

    int  idx[ITEMS];
    bool ok[ITEMS];
    #pragma unroll
    for (int j = 0; j < ITEMS; ++j) {
        idx[j] = base + j * BLKTHREADS;
        ok[j]  = idx[j] < total4;
    }

    // Phase 1: main stream loads, all independent, evict-first (zero reuse)
    float4 v[ITEMS];
    #pragma unroll
    for (int j = 0; j < ITEMS; ++j)
        if (ok[j]) v[j] = __ldcs(&ipt[idx[j]]);

    // Phase 2: scale computation from cached operands
    float sc[ITEMS];
    #pragma unroll
    for (int j = 0; j < ITEMS; ++j) {
        if (ok[j]) {
            const int p  = idx[j] >> 2;        // linear (b,h,w)
            const int w  = p % WIDTH;
            const int bh = p / WIDTH;          // b*HEIGHT + h
            const int b  = bh / HEIGHT;
            const float roi = ((ROI_MASK >> w) & 1u) ? 1.0f : 0.0f;
            const float th = __ldg(&t_o[bh])          * __ldg(&g_inv_t[b]);
            const float sh = __ldg(&s_o[b * WIDTH + w]) * __ldg(&g_inv_s[b]);
            sc[j] = fmaf(th, sh, roi);
        }
    }

    // Phase 3: scale and store (streaming)
    #pragma unroll
    for (int j = 0; j < ITEMS; ++j) {
        if (ok[j]) {
            float4 r = v[j];
            r.x *= sc[j]; r.y *= sc[j]; r.z *= sc[j]; r.w *= sc[j];
            __stcs(&out[idx[j]], r);
        }
    }
}

// ---------------------------------------------------------------------------
// Launch
// ---------------------------------------------------------------------------
extern "C" void kernel_launch(void* const* d_in, const int* in_sizes, int n_in,
                              void* d_out, int out_size)
{
    // Identify inputs by size (robust to metadata ordering):
    //   ipt = B*300*25*16 (largest), t_o = B*300, s_o = B*25
    int ipt_i = 0;
    for (int k = 1; k < n_in; ++k)
        if (in_sizes[k] > in_sizes[ipt_i]) ipt_i = k;
    int a = -1, c = -1;
    for (int k = 0; k < n_in; ++k) {
        if (k == ipt_i) continue;
        if (a < 0) a = k; else c = k;
    }
    int s_i = (in_sizes[a] < in_sizes[c]) ? a : c;
    int t_i = (s_i == a) ? c : a;

    const float* s_o = (const float*)d_in[s_i];
    const float* t_o = (const float*)d_in[t_i];
    const float* ipt = (const float*)d_in[ipt_i];
    float* out = (float*)d_out;

    const int B = in_sizes[t_i] / HEIGHT;   // 1024

    // Kernel 1: inverse norms only (B blocks x 128 threads, ~3us)
    inv_norm_kernel<<<B, 128>>>(s_o, t_o);

    // Kernel 2: stream (4 float4 per thread, 1024 float4 per block)
    const int total4 = out_size / 4;                    // 30,720,000
    const int blocks = (total4 + TILE4 - 1) / TILE4;    // 30,000
    scale_mul_kernel<<<blocks, BLKTHREADS>>>(
        s_o, t_o, (const float4*)ipt, (float4*)out, total4);
}